// round 1
// baseline (speedup 1.0000x reference)
#include <cuda_runtime.h>
#include <cuda_bf16.h>
#include <math.h>

// ---------------- problem constants ----------------
#define S_TOK   1536
#define HID     2880
#define NH      64
#define NKV     8
#define DH      64
#define QKV_DIM 5120           // 64*(64+16)
#define QDIM    4096           // NH*DH
#define KOFF    4096           // k starts here in qkv row
#define VOFF    4608           // v starts here
#define SM_SCALE 0.125f        // 1/sqrt(64)

// ---------------- scratch (device globals; no allocation) ----------------
__device__ float g_t[S_TOK * HID];        // rmsnorm output
__device__ float g_qkv[S_TOK * QKV_DIM];  // qkv (rope applied in place)
__device__ float g_o[S_TOK * QDIM];       // attention output
__device__ float g_cos[S_TOK * 32];
__device__ float g_sin[S_TOK * 32];

// ============================================================
// 1) RMSNorm: one block per token
// ============================================================
__global__ void rmsnorm_kernel(const float* __restrict__ x,
                               const float* __restrict__ scale) {
    int s = blockIdx.x;
    const float4* xr = (const float4*)(x + (size_t)s * HID);
    const float4* sc = (const float4*)scale;
    float4* out = (float4*)(g_t + (size_t)s * HID);

    float ss = 0.f;
    for (int i = threadIdx.x; i < HID / 4; i += blockDim.x) {
        float4 v = xr[i];
        ss += v.x * v.x + v.y * v.y + v.z * v.z + v.w * v.w;
    }
    // warp reduce
    for (int o = 16; o > 0; o >>= 1) ss += __shfl_xor_sync(0xffffffff, ss, o);
    __shared__ float red[8];
    int wid = threadIdx.x >> 5, lid = threadIdx.x & 31;
    if (lid == 0) red[wid] = ss;
    __syncthreads();
    if (wid == 0) {
        float v = (lid < (blockDim.x >> 5)) ? red[lid] : 0.f;
        for (int o = 4; o > 0; o >>= 1) v += __shfl_xor_sync(0xffffffff, v, o);
        if (lid == 0) red[0] = v;
    }
    __syncthreads();
    float r = rsqrtf(red[0] / (float)HID + 1e-5f);

    for (int i = threadIdx.x; i < HID / 4; i += blockDim.x) {
        float4 v = xr[i];
        float4 g = sc[i];
        float4 o4;
        o4.x = v.x * r * g.x; o4.y = v.y * r * g.y;
        o4.z = v.z * r * g.z; o4.w = v.w * r * g.w;
        out[i] = o4;
    }
}

// ============================================================
// 2) SGEMM: C[M,N] = A[M,K] * B[N,K]^T + bias (+ resid)
//    128x128x8 tile, 256 threads, 8x8 micro-tile
// ============================================================
template <bool RESID>
__global__ void __launch_bounds__(256)
sgemm_nt(const float* __restrict__ A, const float* __restrict__ B,
         const float* __restrict__ bias, const float* __restrict__ resid,
         float* __restrict__ C, int M, int N, int K) {
    __shared__ __align__(16) float As[8][128];
    __shared__ __align__(16) float Bs[8][128];

    const int bm = blockIdx.y * 128;
    const int bn = blockIdx.x * 128;
    const int tid = threadIdx.x;
    const int tx = tid & 15;   // 0..15
    const int ty = tid >> 4;   // 0..15

    const int lrow = tid >> 1;        // 0..127
    const int lcol = (tid & 1) * 4;   // 0 or 4

    float acc[8][8];
#pragma unroll
    for (int i = 0; i < 8; i++)
#pragma unroll
        for (int j = 0; j < 8; j++) acc[i][j] = 0.f;

    const bool aok = (bm + lrow) < M;
    const bool bok = (bn + lrow) < N;
    const float* Ap = A + (size_t)(bm + lrow) * K + lcol;
    const float* Bp = B + (size_t)(bn + lrow) * K + lcol;

    for (int k0 = 0; k0 < K; k0 += 8) {
        float4 a4 = make_float4(0, 0, 0, 0), b4 = make_float4(0, 0, 0, 0);
        if (aok) a4 = *(const float4*)(Ap + k0);
        if (bok) b4 = *(const float4*)(Bp + k0);
        As[lcol + 0][lrow] = a4.x; As[lcol + 1][lrow] = a4.y;
        As[lcol + 2][lrow] = a4.z; As[lcol + 3][lrow] = a4.w;
        Bs[lcol + 0][lrow] = b4.x; Bs[lcol + 1][lrow] = b4.y;
        Bs[lcol + 2][lrow] = b4.z; Bs[lcol + 3][lrow] = b4.w;
        __syncthreads();

#pragma unroll
        for (int kk = 0; kk < 8; kk++) {
            const float4* a = (const float4*)&As[kk][0];
            const float4* b = (const float4*)&Bs[kk][0];
            float4 a0 = a[ty], a1 = a[16 + ty];
            float4 b0 = b[tx], b1 = b[16 + tx];
            float ra[8] = {a0.x, a0.y, a0.z, a0.w, a1.x, a1.y, a1.z, a1.w};
            float rb[8] = {b0.x, b0.y, b0.z, b0.w, b1.x, b1.y, b1.z, b1.w};
#pragma unroll
            for (int i = 0; i < 8; i++)
#pragma unroll
                for (int j = 0; j < 8; j++) acc[i][j] = fmaf(ra[i], rb[j], acc[i][j]);
        }
        __syncthreads();
    }

#pragma unroll
    for (int i = 0; i < 8; i++) {
        int row = bm + ((i < 4) ? ty * 4 + i : 64 + ty * 4 + (i - 4));
        if (row >= M) continue;
#pragma unroll
        for (int j = 0; j < 8; j++) {
            int col = bn + ((j < 4) ? tx * 4 + j : 64 + tx * 4 + (j - 4));
            if (col >= N) continue;
            float v = acc[i][j] + bias[col];
            if (RESID) v += resid[(size_t)row * N + col];
            C[(size_t)row * N + col] = v;
        }
    }
}

// ============================================================
// 3) YaRN RoPE tables (double precision, matches reference fp64 path)
// ============================================================
__global__ void rope_tables_kernel() {
    int gid = blockIdx.x * blockDim.x + threadIdx.x;
    if (gid >= S_TOK * 32) return;
    int s = gid >> 5;
    int i = gid & 31;
    const double TWO_PI = 6.283185307179586;
    double freq = pow(150000.0, (double)(2 * i) / 64.0);
    double conc = 0.1 * log(32.0) + 1.0;
    double lo = 32.0 * log(4096.0 / (32.0 * TWO_PI)) / log(150000.0);
    double hi = 32.0 * log(4096.0 / (1.0 * TWO_PI)) / log(150000.0);
    double interp = 1.0 / (32.0 * freq);
    double extrap = 1.0 / freq;
    double ramp = ((double)i - lo) / (hi - lo);
    double mask = 1.0 - fmin(fmax(ramp, 0.0), 1.0);
    double invf = interp * (1.0 - mask) + extrap * mask;
    double f = (double)s * invf;
    g_cos[gid] = (float)(cos(f) * conc);
    g_sin[gid] = (float)(sin(f) * conc);
}

// ============================================================
// 4) RoPE apply (q + k in place). 72 heads (64 q + 8 k), 32 rot pairs each.
// ============================================================
__global__ void rope_apply_kernel() {
    int gid = blockIdx.x * blockDim.x + threadIdx.x;
    const int total = S_TOK * 72 * 32;
    if (gid >= total) return;
    int d = gid & 31;
    int hh = (gid >> 5) % 72;
    int s = gid / (32 * 72);
    float c = g_cos[s * 32 + d];
    float sn = g_sin[s * 32 + d];
    size_t base = (size_t)s * QKV_DIM + ((hh < 64) ? hh * 64 : KOFF + (hh - 64) * 64);
    float x1 = g_qkv[base + d];
    float x2 = g_qkv[base + 32 + d];
    g_qkv[base + d]      = x1 * c - x2 * sn;
    g_qkv[base + 32 + d] = x2 * c + x1 * sn;
}

// ============================================================
// 5) Flash attention with sinks. Block: 128 queries x 1 head.
//    Online softmax seeded m=sink, l=1 (== exp(sink - m)).
// ============================================================
#define ATT_SQ 128
#define ATT_SK 64
#define ATT_SMEM ((2 * ATT_SK * 64 + ATT_SQ * (ATT_SK + 1)) * sizeof(float))

__global__ void attn_kernel(const float* __restrict__ sinks) {
    extern __shared__ float sm[];
    float* Ks = sm;                     // 64 x 64
    float* Vs = sm + ATT_SK * 64;       // 64 x 64
    float* Ss = sm + 2 * ATT_SK * 64;   // 128 x 65

    const int qt = blockIdx.x;
    const int h = blockIdx.y;
    const int t = threadIdx.x;          // 0..127
    const int kv = h & 7;
    const int iq = qt * ATT_SQ + t;

    float q[64];
    {
        const float* qrow = g_qkv + (size_t)iq * QKV_DIM + h * 64;
#pragma unroll
        for (int d4 = 0; d4 < 16; d4++) {
            float4 v = *(const float4*)(qrow + d4 * 4);
            q[d4 * 4 + 0] = v.x * SM_SCALE; q[d4 * 4 + 1] = v.y * SM_SCALE;
            q[d4 * 4 + 2] = v.z * SM_SCALE; q[d4 * 4 + 3] = v.w * SM_SCALE;
        }
    }

    float acc[64];
#pragma unroll
    for (int d = 0; d < 64; d++) acc[d] = 0.f;
    float m = sinks[h];
    float l = 1.0f;

    const int ktmax = (qt * ATT_SQ + ATT_SQ - 1) / ATT_SK;  // 2*qt+1
    for (int kt = 0; kt <= ktmax; kt++) {
        const float* kbase = g_qkv + (size_t)(kt * ATT_SK) * QKV_DIM + KOFF + kv * 64;
        const float* vbase = kbase + (VOFF - KOFF);
        for (int idx = t; idx < ATT_SK * 16; idx += blockDim.x) {
            int r = idx >> 4, c4 = idx & 15;
            *(float4*)(Ks + r * 64 + c4 * 4) = *(const float4*)(kbase + (size_t)r * QKV_DIM + c4 * 4);
            *(float4*)(Vs + r * 64 + c4 * 4) = *(const float4*)(vbase + (size_t)r * QKV_DIM + c4 * 4);
        }
        __syncthreads();

        float rmax = -1e30f;
        for (int j = 0; j < ATT_SK; j++) {
            const float* kj = Ks + j * 64;
            float s = 0.f;
#pragma unroll
            for (int d4 = 0; d4 < 16; d4++) {
                float4 k4 = *(const float4*)(kj + d4 * 4);
                s = fmaf(q[d4 * 4 + 0], k4.x, s);
                s = fmaf(q[d4 * 4 + 1], k4.y, s);
                s = fmaf(q[d4 * 4 + 2], k4.z, s);
                s = fmaf(q[d4 * 4 + 3], k4.w, s);
            }
            int jg = kt * ATT_SK + j;
            s = (jg <= iq) ? s : -1e30f;
            Ss[t * (ATT_SK + 1) + j] = s;
            rmax = fmaxf(rmax, s);
        }

        float mnew = fmaxf(m, rmax);
        float corr = __expf(m - mnew);
        l *= corr;
#pragma unroll
        for (int d = 0; d < 64; d++) acc[d] *= corr;
        m = mnew;

        for (int j = 0; j < ATT_SK; j++) {
            float p = __expf(Ss[t * (ATT_SK + 1) + j] - m);
            l += p;
            const float* vj = Vs + j * 64;
#pragma unroll
            for (int d4 = 0; d4 < 16; d4++) {
                float4 v4 = *(const float4*)(vj + d4 * 4);
                acc[d4 * 4 + 0] = fmaf(p, v4.x, acc[d4 * 4 + 0]);
                acc[d4 * 4 + 1] = fmaf(p, v4.y, acc[d4 * 4 + 1]);
                acc[d4 * 4 + 2] = fmaf(p, v4.z, acc[d4 * 4 + 2]);
                acc[d4 * 4 + 3] = fmaf(p, v4.w, acc[d4 * 4 + 3]);
            }
        }
        __syncthreads();
    }

    float inv = 1.0f / l;
    float* orow = g_o + (size_t)iq * QDIM + h * 64;
#pragma unroll
    for (int d4 = 0; d4 < 16; d4++) {
        float4 v4;
        v4.x = acc[d4 * 4 + 0] * inv; v4.y = acc[d4 * 4 + 1] * inv;
        v4.z = acc[d4 * 4 + 2] * inv; v4.w = acc[d4 * 4 + 3] * inv;
        *(float4*)(orow + d4 * 4) = v4;
    }
}

// ============================================================
// launch
// ============================================================
extern "C" void kernel_launch(void* const* d_in, const int* in_sizes, int n_in,
                              void* d_out, int out_size) {
    const float* x          = (const float*)d_in[0];
    const float* sinks      = (const float*)d_in[1];
    const float* norm_scale = (const float*)d_in[2];
    const float* qkv_w      = (const float*)d_in[3];
    const float* qkv_b      = (const float*)d_in[4];
    const float* out_w      = (const float*)d_in[5];
    const float* out_b      = (const float*)d_in[6];
    float* out = (float*)d_out;

    float* g_t_p;   cudaGetSymbolAddress((void**)&g_t_p, g_t);
    float* g_qkv_p; cudaGetSymbolAddress((void**)&g_qkv_p, g_qkv);
    float* g_o_p;   cudaGetSymbolAddress((void**)&g_o_p, g_o);

    // rope tables (independent of data)
    rope_tables_kernel<<<(S_TOK * 32 + 255) / 256, 256>>>();

    // rmsnorm
    rmsnorm_kernel<<<S_TOK, 256>>>(x, norm_scale);

    // qkv = t @ qkv_w^T + qkv_b   (M=1536, N=5120, K=2880)
    sgemm_nt<false><<<dim3(QKV_DIM / 128, S_TOK / 128), 256>>>(
        g_t_p, qkv_w, qkv_b, nullptr, g_qkv_p, S_TOK, QKV_DIM, HID);

    // rope on q and k in place
    rope_apply_kernel<<<(S_TOK * 72 * 32 + 255) / 256, 256>>>();

    // attention
    cudaFuncSetAttribute(attn_kernel, cudaFuncAttributeMaxDynamicSharedMemorySize,
                         (int)ATT_SMEM);
    attn_kernel<<<dim3(S_TOK / ATT_SQ, NH), ATT_SQ, ATT_SMEM>>>(sinks);

    // y = o @ out_w^T + out_b + x   (M=1536, N=2880, K=4096)
    sgemm_nt<true><<<dim3((HID + 127) / 128, S_TOK / 128), 256>>>(
        g_o_p, out_w, out_b, x, out, S_TOK, HID, QDIM);
}

// round 3
// speedup vs baseline: 1.7988x; 1.7988x over previous
#include <cuda_runtime.h>
#include <cuda_bf16.h>
#include <cstdint>
#include <math.h>

// ---------------- problem constants ----------------
#define S_TOK   1536
#define HID     2880
#define NH      64
#define NKV     8
#define DH      64
#define QKV_DIM 5120
#define QDIM    4096
#define KOFF    4096
#define VOFF    4608
#define SM_SCALE 0.125f

// ---------------- scratch ----------------
__device__ float g_qkv[S_TOK * QKV_DIM];
__device__ __nv_bfloat16 g_t_hi[S_TOK * HID];
__device__ __nv_bfloat16 g_t_lo[S_TOK * HID];
__device__ __nv_bfloat16 g_w1_hi[QKV_DIM * HID];
__device__ __nv_bfloat16 g_w1_lo[QKV_DIM * HID];
__device__ __nv_bfloat16 g_o_hi[S_TOK * QDIM];
__device__ __nv_bfloat16 g_o_lo[S_TOK * QDIM];
__device__ __nv_bfloat16 g_w2_hi[HID * QDIM];
__device__ __nv_bfloat16 g_w2_lo[HID * QDIM];
__device__ float g_cos[S_TOK * 32];
__device__ float g_sin[S_TOK * 32];

// ---------------- helpers ----------------
__device__ __forceinline__ uint32_t smem_u32(const void* p) {
    uint32_t a;
    asm("{ .reg .u64 t; cvta.to.shared.u64 t, %1; cvt.u32.u64 %0, t; }" : "=r"(a) : "l"(p));
    return a;
}

__device__ __forceinline__ void ldsm4(uint32_t* r, uint32_t addr) {
    asm volatile("ldmatrix.sync.aligned.m8n8.x4.shared.b16 {%0,%1,%2,%3}, [%4];"
                 : "=r"(r[0]), "=r"(r[1]), "=r"(r[2]), "=r"(r[3]) : "r"(addr));
}

__device__ __forceinline__ void mma16816(float* c, const uint32_t* a, const uint32_t* b) {
    asm volatile("mma.sync.aligned.m16n8k16.row.col.f32.bf16.bf16.f32 "
                 "{%0,%1,%2,%3}, {%4,%5,%6,%7}, {%8,%9}, {%0,%1,%2,%3};"
                 : "+f"(c[0]), "+f"(c[1]), "+f"(c[2]), "+f"(c[3])
                 : "r"(a[0]), "r"(a[1]), "r"(a[2]), "r"(a[3]), "r"(b[0]), "r"(b[1]));
}

// ============================================================
// 1) RMSNorm -> bf16 hi/lo split
// ============================================================
__global__ void rmsnorm_kernel(const float* __restrict__ x,
                               const float* __restrict__ scale) {
    int s = blockIdx.x;
    const float4* xr = (const float4*)(x + (size_t)s * HID);
    const float4* sc = (const float4*)scale;

    float ss = 0.f;
    for (int i = threadIdx.x; i < HID / 4; i += blockDim.x) {
        float4 v = xr[i];
        ss += v.x * v.x + v.y * v.y + v.z * v.z + v.w * v.w;
    }
    for (int o = 16; o > 0; o >>= 1) ss += __shfl_xor_sync(0xffffffff, ss, o);
    __shared__ float red[8];
    int wid = threadIdx.x >> 5, lid = threadIdx.x & 31;
    if (lid == 0) red[wid] = ss;
    __syncthreads();
    if (wid == 0) {
        float v = (lid < (blockDim.x >> 5)) ? red[lid] : 0.f;
        for (int o = 4; o > 0; o >>= 1) v += __shfl_xor_sync(0xffffffff, v, o);
        if (lid == 0) red[0] = v;
    }
    __syncthreads();
    float r = rsqrtf(red[0] / (float)HID + 1e-5f);

    __nv_bfloat162* th = (__nv_bfloat162*)(g_t_hi + (size_t)s * HID);
    __nv_bfloat162* tl = (__nv_bfloat162*)(g_t_lo + (size_t)s * HID);
    for (int i = threadIdx.x; i < HID / 4; i += blockDim.x) {
        float4 v = xr[i];
        float4 g = sc[i];
        float f0 = v.x * r * g.x, f1 = v.y * r * g.y, f2 = v.z * r * g.z, f3 = v.w * r * g.w;
        __nv_bfloat16 h0 = __float2bfloat16(f0), h1 = __float2bfloat16(f1);
        __nv_bfloat16 h2 = __float2bfloat16(f2), h3 = __float2bfloat16(f3);
        __nv_bfloat162 a, b, c, d;
        a.x = h0; a.y = h1; b.x = h2; b.y = h3;
        c.x = __float2bfloat16(f0 - __bfloat162float(h0));
        c.y = __float2bfloat16(f1 - __bfloat162float(h1));
        d.x = __float2bfloat16(f2 - __bfloat162float(h2));
        d.y = __float2bfloat16(f3 - __bfloat162float(h3));
        th[2 * i] = a; th[2 * i + 1] = b;
        tl[2 * i] = c; tl[2 * i + 1] = d;
    }
}

// ============================================================
// 2) fp32 -> bf16 hi/lo split (weights)
// ============================================================
__global__ void split_kernel(const float4* __restrict__ src,
                             __nv_bfloat162* __restrict__ hi,
                             __nv_bfloat162* __restrict__ lo, int n4) {
    int i = blockIdx.x * blockDim.x + threadIdx.x;
    if (i >= n4) return;
    float4 v = src[i];
    __nv_bfloat16 h0 = __float2bfloat16(v.x), h1 = __float2bfloat16(v.y);
    __nv_bfloat16 h2 = __float2bfloat16(v.z), h3 = __float2bfloat16(v.w);
    __nv_bfloat162 a, b, c, d;
    a.x = h0; a.y = h1; b.x = h2; b.y = h3;
    c.x = __float2bfloat16(v.x - __bfloat162float(h0));
    c.y = __float2bfloat16(v.y - __bfloat162float(h1));
    d.x = __float2bfloat16(v.z - __bfloat162float(h2));
    d.y = __float2bfloat16(v.w - __bfloat162float(h3));
    hi[2 * i] = a; hi[2 * i + 1] = b;
    lo[2 * i] = c; lo[2 * i + 1] = d;
}

// ============================================================
// 3) mma.sync split-bf16 GEMM: C[M,N] = A[M,K] B[N,K]^T + bias (+resid)
//    CTA 128x128x64, 256 threads (2x4 warps, warp tile 64x32)
// ============================================================
#define BM 128
#define BN 128
#define BK 64
#define TILE_B 16384            // 128 rows x 128 bytes
#define STAGE_B (4 * TILE_B)    // Ah, Al, Bh, Bl
#define GEMM_STAGES 3
#define SMEM_TOTAL_GEMM (GEMM_STAGES * STAGE_B + 1024)

// stage one 128x64bf16 tile with SW128 swizzle; 256 threads
__device__ __forceinline__ void load_tile_256(uint32_t sbase, const __nv_bfloat16* __restrict__ g,
                                              int row0, int nrows, int ldk, int k0, int tid) {
#pragma unroll
    for (int u = 0; u < 4; u++) {
        int unit = u * 256 + tid;       // 0..1023
        int r = unit >> 3;              // 0..127
        int c16 = unit & 7;             // 0..7
        uint32_t off = (uint32_t)(r * 128 + ((c16 * 16) ^ ((r & 7) << 4)));
        int gr = row0 + r;
        int ok = (gr < nrows) ? 16 : 0;
        const __nv_bfloat16* src = g + (size_t)((gr < nrows) ? gr : 0) * ldk + k0 + c16 * 8;
        asm volatile("cp.async.cg.shared.global [%0], [%1], 16, %2;"
                     :: "r"(sbase + off), "l"(src), "r"(ok) : "memory");
    }
}

__device__ __forceinline__ void load_stage(uint32_t st,
                                           const __nv_bfloat16* Ah, const __nv_bfloat16* Al,
                                           const __nv_bfloat16* Bh, const __nv_bfloat16* Bl,
                                           int bm, int bn, int M, int N, int K, int k0, int tid) {
    load_tile_256(st,              Ah, bm, M, K, k0, tid);
    load_tile_256(st + TILE_B,     Al, bm, M, K, k0, tid);
    load_tile_256(st + 2 * TILE_B, Bh, bn, N, K, k0, tid);
    load_tile_256(st + 3 * TILE_B, Bl, bn, N, K, k0, tid);
}

template <bool RESID>
__global__ void __launch_bounds__(256, 1)
gemm_mma(const __nv_bfloat16* __restrict__ Ah, const __nv_bfloat16* __restrict__ Al,
         const __nv_bfloat16* __restrict__ Bh, const __nv_bfloat16* __restrict__ Bl,
         const float* __restrict__ bias, const float* __restrict__ resid,
         float* __restrict__ C, int M, int N, int K) {
    extern __shared__ char smem_raw[];
    uint32_t sb = (smem_u32(smem_raw) + 1023u) & ~1023u;

    const int tid = threadIdx.x;
    const int wid = tid >> 5;
    const int lane = tid & 31;
    const int wm = wid & 1;        // 0..1
    const int wn = wid >> 1;       // 0..3
    const int bm = blockIdx.y * BM;
    const int bn = blockIdx.x * BN;

    float acc[4][4][4];
#pragma unroll
    for (int i = 0; i < 4; i++)
#pragma unroll
        for (int j = 0; j < 4; j++)
#pragma unroll
            for (int k = 0; k < 4; k++) acc[i][j][k] = 0.f;

    // ldmatrix per-lane addressing
    const int a_r = wm * 64 + (lane & 15);            // row within A tile (per mt add 16)
    const uint32_t a_cx = (uint32_t)((a_r & 7) << 4); // swizzle xor (invariant to +16)
    const int b_r = wn * 32 + ((lane >> 4) << 3) + (lane & 7); // row within B tile (per pair add 16)
    const uint32_t b_cx = (uint32_t)((b_r & 7) << 4);

    const int NC = K / BK;

    // prologue: chunks 0,1
#pragma unroll
    for (int c = 0; c < 2; c++) {
        load_stage(sb + c * STAGE_B, Ah, Al, Bh, Bl, bm, bn, M, N, K, c * BK, tid);
        asm volatile("cp.async.commit_group;" ::: "memory");
    }

    for (int c = 0; c < NC; c++) {
        int pf = c + 2;
        if (pf < NC) {
            load_stage(sb + (pf % GEMM_STAGES) * STAGE_B, Ah, Al, Bh, Bl, bm, bn, M, N, K, pf * BK, tid);
        }
        asm volatile("cp.async.commit_group;" ::: "memory");
        asm volatile("cp.async.wait_group 2;" ::: "memory");
        __syncthreads();

        const uint32_t st = sb + (c % GEMM_STAGES) * STAGE_B;
#pragma unroll
        for (int ks = 0; ks < 4; ks++) {
            uint32_t ah[4][4], al[4][4], bh[2][4], bl[2][4];
            const uint32_t acb = (uint32_t)(ks * 32 + ((lane >> 4) << 4));
#pragma unroll
            for (int mt = 0; mt < 4; mt++) {
                uint32_t off = (uint32_t)((a_r + mt * 16) * 128) + (acb ^ a_cx);
                ldsm4(ah[mt], st + off);
                ldsm4(al[mt], st + TILE_B + off);
            }
            const uint32_t bcb = (uint32_t)(ks * 32 + ((lane >> 3) & 1) * 16);
#pragma unroll
            for (int p = 0; p < 2; p++) {
                uint32_t off = (uint32_t)((b_r + p * 16) * 128) + (bcb ^ b_cx);
                ldsm4(bh[p], st + 2 * TILE_B + off);
                ldsm4(bl[p], st + 3 * TILE_B + off);
            }
#pragma unroll
            for (int mt = 0; mt < 4; mt++) {
#pragma unroll
                for (int nt = 0; nt < 4; nt++) {
                    const uint32_t* bhp = &bh[nt >> 1][(nt & 1) * 2];
                    const uint32_t* blp = &bl[nt >> 1][(nt & 1) * 2];
                    mma16816(acc[mt][nt], ah[mt], bhp);
                    mma16816(acc[mt][nt], al[mt], bhp);
                    mma16816(acc[mt][nt], ah[mt], blp);
                }
            }
        }
        __syncthreads();
    }

    // epilogue
    const int row0 = bm + wm * 64;
    const int col0 = bn + wn * 32;
#pragma unroll
    for (int mt = 0; mt < 4; mt++) {
#pragma unroll
        for (int nt = 0; nt < 4; nt++) {
            int r = row0 + mt * 16 + (lane >> 2);
            int c0 = col0 + nt * 8 + (lane & 3) * 2;
            if (c0 < N) {
                float bx = bias[c0], by = bias[c0 + 1];
                float* p0 = C + (size_t)r * N + c0;
                float* p1 = C + (size_t)(r + 8) * N + c0;
                float2 v0, v1;
                v0.x = acc[mt][nt][0] + bx; v0.y = acc[mt][nt][1] + by;
                v1.x = acc[mt][nt][2] + bx; v1.y = acc[mt][nt][3] + by;
                if (RESID) {
                    const float2 x0 = *(const float2*)(resid + (size_t)r * N + c0);
                    const float2 x1 = *(const float2*)(resid + (size_t)(r + 8) * N + c0);
                    v0.x += x0.x; v0.y += x0.y;
                    v1.x += x1.x; v1.y += x1.y;
                }
                *(float2*)p0 = v0;
                *(float2*)p1 = v1;
            }
        }
    }
}

// ============================================================
// 4) YaRN RoPE tables (fp64, matches reference)
// ============================================================
__global__ void rope_tables_kernel() {
    int gid = blockIdx.x * blockDim.x + threadIdx.x;
    if (gid >= S_TOK * 32) return;
    int s = gid >> 5;
    int i = gid & 31;
    const double TWO_PI = 6.283185307179586;
    double freq = pow(150000.0, (double)(2 * i) / 64.0);
    double conc = 0.1 * log(32.0) + 1.0;
    double lo = 32.0 * log(4096.0 / (32.0 * TWO_PI)) / log(150000.0);
    double hi = 32.0 * log(4096.0 / (1.0 * TWO_PI)) / log(150000.0);
    double interp = 1.0 / (32.0 * freq);
    double extrap = 1.0 / freq;
    double ramp = ((double)i - lo) / (hi - lo);
    double mask = 1.0 - fmin(fmax(ramp, 0.0), 1.0);
    double invf = interp * (1.0 - mask) + extrap * mask;
    double f = (double)s * invf;
    g_cos[gid] = (float)(cos(f) * conc);
    g_sin[gid] = (float)(sin(f) * conc);
}

// ============================================================
// 5) RoPE apply in place on q + k
// ============================================================
__global__ void rope_apply_kernel() {
    int gid = blockIdx.x * blockDim.x + threadIdx.x;
    const int total = S_TOK * 72 * 32;
    if (gid >= total) return;
    int d = gid & 31;
    int hh = (gid >> 5) % 72;
    int s = gid / (32 * 72);
    float c = g_cos[s * 32 + d];
    float sn = g_sin[s * 32 + d];
    size_t base = (size_t)s * QKV_DIM + ((hh < 64) ? hh * 64 : KOFF + (hh - 64) * 64);
    float x1 = g_qkv[base + d];
    float x2 = g_qkv[base + 32 + d];
    g_qkv[base + d]      = x1 * c - x2 * sn;
    g_qkv[base + 32 + d] = x2 * c + x1 * sn;
}

// ============================================================
// 6) Flash attention with sinks (fp32); epilogue emits bf16 hi/lo split
// ============================================================
#define ATT_SQ 128
#define ATT_SK 64
#define ATT_SMEM ((2 * ATT_SK * 64 + ATT_SQ * (ATT_SK + 1)) * sizeof(float))

__global__ void attn_kernel(const float* __restrict__ sinks) {
    extern __shared__ float sm[];
    float* Ks = sm;
    float* Vs = sm + ATT_SK * 64;
    float* Ss = sm + 2 * ATT_SK * 64;

    const int qt = blockIdx.x;
    const int h = blockIdx.y;
    const int t = threadIdx.x;
    const int kv = h & 7;
    const int iq = qt * ATT_SQ + t;

    float q[64];
    {
        const float* qrow = g_qkv + (size_t)iq * QKV_DIM + h * 64;
#pragma unroll
        for (int d4 = 0; d4 < 16; d4++) {
            float4 v = *(const float4*)(qrow + d4 * 4);
            q[d4 * 4 + 0] = v.x * SM_SCALE; q[d4 * 4 + 1] = v.y * SM_SCALE;
            q[d4 * 4 + 2] = v.z * SM_SCALE; q[d4 * 4 + 3] = v.w * SM_SCALE;
        }
    }

    float acc[64];
#pragma unroll
    for (int d = 0; d < 64; d++) acc[d] = 0.f;
    float m = sinks[h];
    float l = 1.0f;

    const int ktmax = (qt * ATT_SQ + ATT_SQ - 1) / ATT_SK;
    for (int kt = 0; kt <= ktmax; kt++) {
        const float* kbase = g_qkv + (size_t)(kt * ATT_SK) * QKV_DIM + KOFF + kv * 64;
        const float* vbase = kbase + (VOFF - KOFF);
        for (int idx = t; idx < ATT_SK * 16; idx += blockDim.x) {
            int r = idx >> 4, c4 = idx & 15;
            *(float4*)(Ks + r * 64 + c4 * 4) = *(const float4*)(kbase + (size_t)r * QKV_DIM + c4 * 4);
            *(float4*)(Vs + r * 64 + c4 * 4) = *(const float4*)(vbase + (size_t)r * QKV_DIM + c4 * 4);
        }
        __syncthreads();

        float rmax = -1e30f;
        for (int j = 0; j < ATT_SK; j++) {
            const float* kj = Ks + j * 64;
            float s = 0.f;
#pragma unroll
            for (int d4 = 0; d4 < 16; d4++) {
                float4 k4 = *(const float4*)(kj + d4 * 4);
                s = fmaf(q[d4 * 4 + 0], k4.x, s);
                s = fmaf(q[d4 * 4 + 1], k4.y, s);
                s = fmaf(q[d4 * 4 + 2], k4.z, s);
                s = fmaf(q[d4 * 4 + 3], k4.w, s);
            }
            int jg = kt * ATT_SK + j;
            s = (jg <= iq) ? s : -1e30f;
            Ss[t * (ATT_SK + 1) + j] = s;
            rmax = fmaxf(rmax, s);
        }

        float mnew = fmaxf(m, rmax);
        float corr = __expf(m - mnew);
        l *= corr;
#pragma unroll
        for (int d = 0; d < 64; d++) acc[d] *= corr;
        m = mnew;

        for (int j = 0; j < ATT_SK; j++) {
            float p = __expf(Ss[t * (ATT_SK + 1) + j] - m);
            l += p;
            const float* vj = Vs + j * 64;
#pragma unroll
            for (int d4 = 0; d4 < 16; d4++) {
                float4 v4 = *(const float4*)(vj + d4 * 4);
                acc[d4 * 4 + 0] = fmaf(p, v4.x, acc[d4 * 4 + 0]);
                acc[d4 * 4 + 1] = fmaf(p, v4.y, acc[d4 * 4 + 1]);
                acc[d4 * 4 + 2] = fmaf(p, v4.z, acc[d4 * 4 + 2]);
                acc[d4 * 4 + 3] = fmaf(p, v4.w, acc[d4 * 4 + 3]);
            }
        }
        __syncthreads();
    }

    float inv = 1.0f / l;
    size_t ob = (size_t)iq * QDIM + h * 64;
#pragma unroll
    for (int d2 = 0; d2 < 32; d2++) {
        float v0 = acc[2 * d2] * inv, v1 = acc[2 * d2 + 1] * inv;
        __nv_bfloat16 h0 = __float2bfloat16(v0), h1 = __float2bfloat16(v1);
        __nv_bfloat162 hh, ll;
        hh.x = h0; hh.y = h1;
        ll.x = __float2bfloat16(v0 - __bfloat162float(h0));
        ll.y = __float2bfloat16(v1 - __bfloat162float(h1));
        *(__nv_bfloat162*)(g_o_hi + ob + 2 * d2) = hh;
        *(__nv_bfloat162*)(g_o_lo + ob + 2 * d2) = ll;
    }
}

// ============================================================
// launch
// ============================================================
extern "C" void kernel_launch(void* const* d_in, const int* in_sizes, int n_in,
                              void* d_out, int out_size) {
    const float* x          = (const float*)d_in[0];
    const float* sinks      = (const float*)d_in[1];
    const float* norm_scale = (const float*)d_in[2];
    const float* qkv_w      = (const float*)d_in[3];
    const float* qkv_b      = (const float*)d_in[4];
    const float* out_w      = (const float*)d_in[5];
    const float* out_b      = (const float*)d_in[6];
    float* out = (float*)d_out;

    float* g_qkv_p;          cudaGetSymbolAddress((void**)&g_qkv_p, g_qkv);
    __nv_bfloat16 *th, *tl, *w1h, *w1l, *oh, *ol, *w2h, *w2l;
    cudaGetSymbolAddress((void**)&th, g_t_hi);   cudaGetSymbolAddress((void**)&tl, g_t_lo);
    cudaGetSymbolAddress((void**)&w1h, g_w1_hi); cudaGetSymbolAddress((void**)&w1l, g_w1_lo);
    cudaGetSymbolAddress((void**)&oh, g_o_hi);   cudaGetSymbolAddress((void**)&ol, g_o_lo);
    cudaGetSymbolAddress((void**)&w2h, g_w2_hi); cudaGetSymbolAddress((void**)&w2l, g_w2_lo);

    cudaFuncSetAttribute(gemm_mma<false>, cudaFuncAttributeMaxDynamicSharedMemorySize, SMEM_TOTAL_GEMM);
    cudaFuncSetAttribute(gemm_mma<true>,  cudaFuncAttributeMaxDynamicSharedMemorySize, SMEM_TOTAL_GEMM);
    cudaFuncSetAttribute(attn_kernel, cudaFuncAttributeMaxDynamicSharedMemorySize, (int)ATT_SMEM);

    // rope tables + weight splits
    rope_tables_kernel<<<(S_TOK * 32 + 255) / 256, 256>>>();
    {
        int n4 = QKV_DIM * HID / 4;
        split_kernel<<<(n4 + 255) / 256, 256>>>((const float4*)qkv_w,
                                                (__nv_bfloat162*)w1h, (__nv_bfloat162*)w1l, n4);
    }
    {
        int n4 = HID * QDIM / 4;
        split_kernel<<<(n4 + 255) / 256, 256>>>((const float4*)out_w,
                                                (__nv_bfloat162*)w2h, (__nv_bfloat162*)w2l, n4);
    }

    // rmsnorm (writes bf16 hi/lo)
    rmsnorm_kernel<<<S_TOK, 256>>>(x, norm_scale);

    // qkv = t @ qkv_w^T + qkv_b   (M=1536, N=5120, K=2880) — tensor cores via mma.sync
    gemm_mma<false><<<dim3(QKV_DIM / BN, S_TOK / BM), 256, SMEM_TOTAL_GEMM>>>(
        th, tl, w1h, w1l, qkv_b, nullptr, g_qkv_p, S_TOK, QKV_DIM, HID);

    // rope in place
    rope_apply_kernel<<<(S_TOK * 72 * 32 + 255) / 256, 256>>>();

    // attention (writes bf16 hi/lo of o)
    attn_kernel<<<dim3(S_TOK / ATT_SQ, NH), ATT_SQ, ATT_SMEM>>>(sinks);

    // y = o @ out_w^T + out_b + x   (M=1536, N=2880, K=4096) — tensor cores via mma.sync
    gemm_mma<true><<<dim3((HID + BN - 1) / BN, S_TOK / BM), 256, SMEM_TOTAL_GEMM>>>(
        oh, ol, w2h, w2l, out_b, x, out, S_TOK, HID, QDIM);
}

// round 4
// speedup vs baseline: 4.0253x; 2.2377x over previous
#include <cuda_runtime.h>
#include <cuda_fp16.h>
#include <cstdint>
#include <math.h>

// ---------------- problem constants ----------------
#define S_TOK   1536
#define HID     2880
#define NH      64
#define NKV     8
#define DH      64
#define QKV_DIM 5120
#define QDIM    4096
#define KOFF    4096
#define VOFF    4608
#define SM_SCALE 0.125f

// ---------------- scratch ----------------
__device__ float g_qkv[S_TOK * QKV_DIM];
__device__ __half g_t_h[S_TOK * HID];
__device__ __half g_t_l[S_TOK * HID];
__device__ __half g_w1[QKV_DIM * HID];
__device__ __half g_w2[HID * QDIM];
__device__ __half g_q_h[S_TOK * QDIM];
__device__ __half g_q_l[S_TOK * QDIM];
__device__ __half g_k_h[NKV * S_TOK * DH];
__device__ __half g_k_l[NKV * S_TOK * DH];
__device__ __half g_vt_h[NKV * DH * S_TOK];
__device__ __half g_vt_l[NKV * DH * S_TOK];
__device__ __half g_o_h[S_TOK * QDIM];
__device__ __half g_o_l[S_TOK * QDIM];
__device__ float g_cos[S_TOK * 32];
__device__ float g_sin[S_TOK * 32];

// ---------------- helpers ----------------
__device__ __forceinline__ uint32_t smem_u32(const void* p) {
    uint32_t a;
    asm("{ .reg .u64 t; cvta.to.shared.u64 t, %1; cvt.u32.u64 %0, t; }" : "=r"(a) : "l"(p));
    return a;
}

__device__ __forceinline__ void ldsm4(uint32_t* r, uint32_t addr) {
    asm volatile("ldmatrix.sync.aligned.m8n8.x4.shared.b16 {%0,%1,%2,%3}, [%4];"
                 : "=r"(r[0]), "=r"(r[1]), "=r"(r[2]), "=r"(r[3]) : "r"(addr));
}

__device__ __forceinline__ void mma_f16(float* c, const uint32_t* a, const uint32_t* b) {
    asm volatile("mma.sync.aligned.m16n8k16.row.col.f32.f16.f16.f32 "
                 "{%0,%1,%2,%3}, {%4,%5,%6,%7}, {%8,%9}, {%0,%1,%2,%3};"
                 : "+f"(c[0]), "+f"(c[1]), "+f"(c[2]), "+f"(c[3])
                 : "r"(a[0]), "r"(a[1]), "r"(a[2]), "r"(a[3]), "r"(b[0]), "r"(b[1]));
}

__device__ __forceinline__ uint32_t pack_h2(float a, float b) {
    __half2 h = __floats2half2_rn(a, b);
    return *(uint32_t*)&h;
}

// ============================================================
// 1) RMSNorm -> fp16 hi/lo split
// ============================================================
__global__ void rmsnorm_kernel(const float* __restrict__ x,
                               const float* __restrict__ scale) {
    int s = blockIdx.x;
    const float4* xr = (const float4*)(x + (size_t)s * HID);
    const float4* sc = (const float4*)scale;

    float ss = 0.f;
    for (int i = threadIdx.x; i < HID / 4; i += blockDim.x) {
        float4 v = xr[i];
        ss += v.x * v.x + v.y * v.y + v.z * v.z + v.w * v.w;
    }
    for (int o = 16; o > 0; o >>= 1) ss += __shfl_xor_sync(0xffffffff, ss, o);
    __shared__ float red[8];
    int wid = threadIdx.x >> 5, lid = threadIdx.x & 31;
    if (lid == 0) red[wid] = ss;
    __syncthreads();
    if (wid == 0) {
        float v = (lid < (blockDim.x >> 5)) ? red[lid] : 0.f;
        for (int o = 4; o > 0; o >>= 1) v += __shfl_xor_sync(0xffffffff, v, o);
        if (lid == 0) red[0] = v;
    }
    __syncthreads();
    float r = rsqrtf(red[0] / (float)HID + 1e-5f);

    uint2* th = (uint2*)(g_t_h + (size_t)s * HID);
    uint2* tl = (uint2*)(g_t_l + (size_t)s * HID);
    for (int i = threadIdx.x; i < HID / 4; i += blockDim.x) {
        float4 v = xr[i];
        float4 g = sc[i];
        float f0 = v.x * r * g.x, f1 = v.y * r * g.y, f2 = v.z * r * g.z, f3 = v.w * r * g.w;
        __half h0 = __float2half_rn(f0), h1 = __float2half_rn(f1);
        __half h2 = __float2half_rn(f2), h3 = __float2half_rn(f3);
        uint2 hh, ll;
        hh.x = pack_h2(f0, f1); hh.y = pack_h2(f2, f3);
        ll.x = pack_h2(f0 - __half2float(h0), f1 - __half2float(h1));
        ll.y = pack_h2(f2 - __half2float(h2), f3 - __half2float(h3));
        th[i] = hh; tl[i] = ll;
    }
}

// ============================================================
// 2) fp32 -> fp16 convert (weights, hi only)
// ============================================================
__global__ void convert_h_kernel(const float4* __restrict__ src,
                                 uint2* __restrict__ dst, int n4) {
    int i = blockIdx.x * blockDim.x + threadIdx.x;
    if (i >= n4) return;
    float4 v = src[i];
    uint2 o;
    o.x = pack_h2(v.x, v.y);
    o.y = pack_h2(v.z, v.w);
    dst[i] = o;
}

// ============================================================
// 3) mma.sync fp16 2-term GEMM: C = A(hi+lo) B(hi)^T + bias (+resid)
//    CTA 128x128x64, 256 threads
// ============================================================
#define BM 128
#define BN 128
#define BK 64
#define TILE_B 16384            // 128 rows x 128 bytes
#define STAGE_B (3 * TILE_B)    // Ah, Al, Bh
#define GEMM_STAGES 3
#define SMEM_TOTAL_GEMM (GEMM_STAGES * STAGE_B + 1024)

__device__ __forceinline__ void load_tile_256(uint32_t sbase, const __half* __restrict__ g,
                                              int row0, int nrows, int ldk, int k0, int tid) {
#pragma unroll
    for (int u = 0; u < 4; u++) {
        int unit = u * 256 + tid;
        int r = unit >> 3;
        int c16 = unit & 7;
        uint32_t off = (uint32_t)(r * 128 + ((c16 * 16) ^ ((r & 7) << 4)));
        int gr = row0 + r;
        int ok = (gr < nrows) ? 16 : 0;
        const __half* src = g + (size_t)((gr < nrows) ? gr : 0) * ldk + k0 + c16 * 8;
        asm volatile("cp.async.cg.shared.global [%0], [%1], 16, %2;"
                     :: "r"(sbase + off), "l"(src), "r"(ok) : "memory");
    }
}

__device__ __forceinline__ void load_stage(uint32_t st,
                                           const __half* Ah, const __half* Al, const __half* Bh,
                                           int bm, int bn, int M, int N, int K, int k0, int tid) {
    load_tile_256(st,              Ah, bm, M, K, k0, tid);
    load_tile_256(st + TILE_B,     Al, bm, M, K, k0, tid);
    load_tile_256(st + 2 * TILE_B, Bh, bn, N, K, k0, tid);
}

template <bool RESID>
__global__ void __launch_bounds__(256, 1)
gemm_mma(const __half* __restrict__ Ah, const __half* __restrict__ Al,
         const __half* __restrict__ Bh,
         const float* __restrict__ bias, const float* __restrict__ resid,
         float* __restrict__ C, int M, int N, int K) {
    extern __shared__ char smem_raw[];
    uint32_t sb = (smem_u32(smem_raw) + 1023u) & ~1023u;

    const int tid = threadIdx.x;
    const int wid = tid >> 5;
    const int lane = tid & 31;
    const int wm = wid & 1;
    const int wn = wid >> 1;
    const int bm = blockIdx.y * BM;
    const int bn = blockIdx.x * BN;

    float acc[4][4][4];
#pragma unroll
    for (int i = 0; i < 4; i++)
#pragma unroll
        for (int j = 0; j < 4; j++)
#pragma unroll
            for (int k = 0; k < 4; k++) acc[i][j][k] = 0.f;

    const int a_r = wm * 64 + (lane & 15);
    const uint32_t a_cx = (uint32_t)((a_r & 7) << 4);
    const int b_r = wn * 32 + ((lane >> 4) << 3) + (lane & 7);
    const uint32_t b_cx = (uint32_t)((b_r & 7) << 4);

    const int NC = K / BK;

#pragma unroll
    for (int c = 0; c < 2; c++) {
        load_stage(sb + c * STAGE_B, Ah, Al, Bh, bm, bn, M, N, K, c * BK, tid);
        asm volatile("cp.async.commit_group;" ::: "memory");
    }

    for (int c = 0; c < NC; c++) {
        int pf = c + 2;
        if (pf < NC) {
            load_stage(sb + (pf % GEMM_STAGES) * STAGE_B, Ah, Al, Bh, bm, bn, M, N, K, pf * BK, tid);
        }
        asm volatile("cp.async.commit_group;" ::: "memory");
        asm volatile("cp.async.wait_group 2;" ::: "memory");
        __syncthreads();

        const uint32_t st = sb + (c % GEMM_STAGES) * STAGE_B;
#pragma unroll
        for (int ks = 0; ks < 4; ks++) {
            uint32_t ah[4][4], al[4][4], bh[2][4];
            const uint32_t acb = (uint32_t)(ks * 32 + ((lane >> 4) << 4));
#pragma unroll
            for (int mt = 0; mt < 4; mt++) {
                uint32_t off = (uint32_t)((a_r + mt * 16) * 128) + (acb ^ a_cx);
                ldsm4(ah[mt], st + off);
                ldsm4(al[mt], st + TILE_B + off);
            }
            const uint32_t bcb = (uint32_t)(ks * 32 + ((lane >> 3) & 1) * 16);
#pragma unroll
            for (int p = 0; p < 2; p++) {
                uint32_t off = (uint32_t)((b_r + p * 16) * 128) + (bcb ^ b_cx);
                ldsm4(bh[p], st + 2 * TILE_B + off);
            }
#pragma unroll
            for (int mt = 0; mt < 4; mt++) {
#pragma unroll
                for (int nt = 0; nt < 4; nt++) {
                    const uint32_t* bhp = &bh[nt >> 1][(nt & 1) * 2];
                    mma_f16(acc[mt][nt], ah[mt], bhp);
                    mma_f16(acc[mt][nt], al[mt], bhp);
                }
            }
        }
        __syncthreads();
    }

    const int row0 = bm + wm * 64;
    const int col0 = bn + wn * 32;
#pragma unroll
    for (int mt = 0; mt < 4; mt++) {
#pragma unroll
        for (int nt = 0; nt < 4; nt++) {
            int r = row0 + mt * 16 + (lane >> 2);
            int c0 = col0 + nt * 8 + (lane & 3) * 2;
            if (c0 < N) {
                float bx = bias[c0], by = bias[c0 + 1];
                float2 v0, v1;
                v0.x = acc[mt][nt][0] + bx; v0.y = acc[mt][nt][1] + by;
                v1.x = acc[mt][nt][2] + bx; v1.y = acc[mt][nt][3] + by;
                if (RESID) {
                    const float2 x0 = *(const float2*)(resid + (size_t)r * N + c0);
                    const float2 x1 = *(const float2*)(resid + (size_t)(r + 8) * N + c0);
                    v0.x += x0.x; v0.y += x0.y;
                    v1.x += x1.x; v1.y += x1.y;
                }
                *(float2*)(C + (size_t)r * N + c0) = v0;
                *(float2*)(C + (size_t)(r + 8) * N + c0) = v1;
            }
        }
    }
}

// ============================================================
// 4) YaRN RoPE tables (fp64, matches reference)
// ============================================================
__global__ void rope_tables_kernel() {
    int gid = blockIdx.x * blockDim.x + threadIdx.x;
    if (gid >= S_TOK * 32) return;
    int s = gid >> 5;
    int i = gid & 31;
    const double TWO_PI = 6.283185307179586;
    double freq = pow(150000.0, (double)(2 * i) / 64.0);
    double conc = 0.1 * log(32.0) + 1.0;
    double lo = 32.0 * log(4096.0 / (32.0 * TWO_PI)) / log(150000.0);
    double hi = 32.0 * log(4096.0 / (1.0 * TWO_PI)) / log(150000.0);
    double interp = 1.0 / (32.0 * freq);
    double extrap = 1.0 / freq;
    double ramp = ((double)i - lo) / (hi - lo);
    double mask = 1.0 - fmin(fmax(ramp, 0.0), 1.0);
    double invf = interp * (1.0 - mask) + extrap * mask;
    double f = (double)s * invf;
    g_cos[gid] = (float)(cos(f) * conc);
    g_sin[gid] = (float)(sin(f) * conc);
}

// ============================================================
// 5) prep: rope + scale + fp16 hi/lo split of q,k ; v split+transpose
// ============================================================
__global__ void __launch_bounds__(128)
prep_attn_kernel() {
    int s = blockIdx.x;
    int tid = threadIdx.x;
    __shared__ float cs[32], sn[32];
    if (tid < 32) { cs[tid] = g_cos[s * 32 + tid]; sn[tid] = g_sin[s * 32 + tid]; }
    __syncthreads();
    const float* row = g_qkv + (size_t)s * QKV_DIM;

    // q: 64 heads x 32 rotation pairs, scaled
    for (int i = tid; i < 2048; i += 128) {
        int hh = i >> 5, d = i & 31;
        float x1 = row[hh * 64 + d], x2 = row[hh * 64 + 32 + d];
        float c = cs[d], ss = sn[d];
        float r1 = (x1 * c - x2 * ss) * SM_SCALE;
        float r2 = (x2 * c + x1 * ss) * SM_SCALE;
        size_t o = (size_t)s * QDIM + hh * 64 + d;
        __half h1 = __float2half_rn(r1), h2 = __float2half_rn(r2);
        g_q_h[o] = h1; g_q_h[o + 32] = h2;
        g_q_l[o] = __float2half_rn(r1 - __half2float(h1));
        g_q_l[o + 32] = __float2half_rn(r2 - __half2float(h2));
    }
    // k: 8 kv heads x 32 pairs, layout [kv][s][64]
    for (int i = tid; i < 256; i += 128) {
        int kvh = i >> 5, d = i & 31;
        float x1 = row[KOFF + kvh * 64 + d], x2 = row[KOFF + kvh * 64 + 32 + d];
        float c = cs[d], ss = sn[d];
        float r1 = x1 * c - x2 * ss;
        float r2 = x2 * c + x1 * ss;
        size_t o = (size_t)kvh * S_TOK * DH + (size_t)s * DH + d;
        __half h1 = __float2half_rn(r1), h2 = __float2half_rn(r2);
        g_k_h[o] = h1; g_k_h[o + 32] = h2;
        g_k_l[o] = __float2half_rn(r1 - __half2float(h1));
        g_k_l[o + 32] = __float2half_rn(r2 - __half2float(h2));
    }
    // v: split + transpose -> [kv][d][s]
    for (int i = tid; i < 512; i += 128) {
        int kvh = i >> 6, d = i & 63;
        float v = row[VOFF + kvh * 64 + d];
        size_t o = (size_t)kvh * DH * S_TOK + (size_t)d * S_TOK + s;
        __half h = __float2half_rn(v);
        g_vt_h[o] = h;
        g_vt_l[o] = __float2half_rn(v - __half2float(h));
    }
}

// ============================================================
// 6) tensorized flash attention with sinks
//    block: 64 q rows x 1 head, 4 warps (16 rows each)
// ============================================================
#define ATT_SMEM_TOTAL (1024 + 16384 + 2 * 32768)

__device__ __forceinline__ void stage64(uint32_t sbase, const __half* __restrict__ g,
                                        int row_stride, int tid) {
#pragma unroll
    for (int u = 0; u < 4; u++) {
        int unit = u * 128 + tid;
        int r = unit >> 3, c16 = unit & 7;
        uint32_t off = (uint32_t)(r * 128 + ((c16 * 16) ^ ((r & 7) << 4)));
        const __half* src = g + (size_t)r * row_stride + c16 * 8;
        asm volatile("cp.async.cg.shared.global [%0], [%1], 16;"
                     :: "r"(sbase + off), "l"(src) : "memory");
    }
}

__device__ __forceinline__ void stage_kv(uint32_t base, int kt, int kv, int tid) {
    const __half* kh = g_k_h + (size_t)kv * S_TOK * DH + (size_t)kt * 64 * DH;
    const __half* kl = g_k_l + (size_t)kv * S_TOK * DH + (size_t)kt * 64 * DH;
    const __half* vh = g_vt_h + (size_t)kv * DH * S_TOK + kt * 64;
    const __half* vl = g_vt_l + (size_t)kv * DH * S_TOK + kt * 64;
    stage64(base,         kh, DH, tid);
    stage64(base + 8192,  kl, DH, tid);
    stage64(base + 16384, vh, S_TOK, tid);
    stage64(base + 24576, vl, S_TOK, tid);
}

__global__ void __launch_bounds__(128)
attn_mma_kernel(const float* __restrict__ sinks) {
    extern __shared__ char sraw[];
    uint32_t sb = (smem_u32(sraw) + 1023u) & ~1023u;
    const uint32_t QHB = sb, QLB = sb + 8192, KVB = sb + 16384;

    const int qt = blockIdx.x, h = blockIdx.y, kv = h & 7;
    const int tid = threadIdx.x, w = tid >> 5, lane = tid & 31;

    // prologue: stage Q (hi/lo) + KV tile 0
    stage64(QHB, g_q_h + (size_t)(qt * 64) * QDIM + h * 64, QDIM, tid);
    stage64(QLB, g_q_l + (size_t)(qt * 64) * QDIM + h * 64, QDIM, tid);
    stage_kv(KVB, 0, kv, tid);
    asm volatile("cp.async.commit_group;" ::: "memory");
    asm volatile("cp.async.wait_group 0;" ::: "memory");
    __syncthreads();

    // Q fragments (persistent)
    uint32_t qh[4][4], ql[4][4];
    {
        int a_r = w * 16 + (lane & 15);
        uint32_t ax = (uint32_t)((a_r & 7) << 4);
#pragma unroll
        for (int kt4 = 0; kt4 < 4; kt4++) {
            uint32_t cb = (uint32_t)(kt4 * 32 + ((lane >> 4) << 4));
            uint32_t off = (uint32_t)(a_r * 128) + (cb ^ ax);
            ldsm4(qh[kt4], QHB + off);
            ldsm4(ql[kt4], QLB + off);
        }
    }

    float O[8][4];
#pragma unroll
    for (int nt = 0; nt < 8; nt++)
#pragma unroll
        for (int j = 0; j < 4; j++) O[nt][j] = 0.f;

    float mA = sinks[h], mB = mA, lA = 1.f, lB = 1.f;
    const int q0 = qt * 64 + w * 16 + (lane >> 2);
    const int b_rbase = ((lane >> 4) << 3) + (lane & 7);
    const uint32_t bsel = (uint32_t)(((lane >> 3) & 1) * 16);

    for (int kt = 0; kt <= qt; kt++) {
        if (kt + 1 <= qt)
            stage_kv(KVB + ((kt + 1) & 1) * 32768, kt + 1, kv, tid);
        asm volatile("cp.async.commit_group;" ::: "memory");
        asm volatile("cp.async.wait_group 1;" ::: "memory");
        __syncthreads();

        const uint32_t kb  = KVB + (kt & 1) * 32768;
        const uint32_t klb = kb + 8192, vb = kb + 16384, vlb = kb + 24576;

        // scores
        float sc[8][4];
#pragma unroll
        for (int nt = 0; nt < 8; nt++)
#pragma unroll
            for (int j = 0; j < 4; j++) sc[nt][j] = 0.f;

#pragma unroll
        for (int kt4 = 0; kt4 < 4; kt4++) {
#pragma unroll
            for (int kg = 0; kg < 4; kg++) {
                int b_r = kg * 16 + b_rbase;
                uint32_t off = (uint32_t)(b_r * 128) + (((uint32_t)(kt4 * 32) + bsel) ^ ((uint32_t)((b_r & 7) << 4)));
                uint32_t bh4[4], bl4[4];
                ldsm4(bh4, kb + off);
                ldsm4(bl4, klb + off);
#pragma unroll
                for (int n2 = 0; n2 < 2; n2++) {
                    float* s = sc[2 * kg + n2];
                    mma_f16(s, qh[kt4], &bh4[n2 * 2]);
                    mma_f16(s, ql[kt4], &bh4[n2 * 2]);
                    mma_f16(s, qh[kt4], &bl4[n2 * 2]);
                }
            }
        }

        // causal mask (diagonal tile only)
        if (kt == qt) {
#pragma unroll
            for (int nt = 0; nt < 8; nt++) {
                int key = kt * 64 + nt * 8 + 2 * (lane & 3);
                if (key > q0)       sc[nt][0] = -1e30f;
                if (key + 1 > q0)   sc[nt][1] = -1e30f;
                if (key > q0 + 8)   sc[nt][2] = -1e30f;
                if (key + 1 > q0 + 8) sc[nt][3] = -1e30f;
            }
        }

        // online softmax
        float r0 = -1e30f, r1 = -1e30f;
#pragma unroll
        for (int nt = 0; nt < 8; nt++) {
            r0 = fmaxf(r0, fmaxf(sc[nt][0], sc[nt][1]));
            r1 = fmaxf(r1, fmaxf(sc[nt][2], sc[nt][3]));
        }
        r0 = fmaxf(r0, __shfl_xor_sync(0xffffffffu, r0, 1));
        r0 = fmaxf(r0, __shfl_xor_sync(0xffffffffu, r0, 2));
        r1 = fmaxf(r1, __shfl_xor_sync(0xffffffffu, r1, 1));
        r1 = fmaxf(r1, __shfl_xor_sync(0xffffffffu, r1, 2));
        float mA2 = fmaxf(mA, r0), mB2 = fmaxf(mB, r1);
        float cA = __expf(mA - mA2), cB = __expf(mB - mB2);
        mA = mA2; mB = mB2;

        float sA = 0.f, sB = 0.f;
#pragma unroll
        for (int nt = 0; nt < 8; nt++) {
            sc[nt][0] = __expf(sc[nt][0] - mA);
            sc[nt][1] = __expf(sc[nt][1] - mA);
            sc[nt][2] = __expf(sc[nt][2] - mB);
            sc[nt][3] = __expf(sc[nt][3] - mB);
            sA += sc[nt][0] + sc[nt][1];
            sB += sc[nt][2] + sc[nt][3];
        }
        sA += __shfl_xor_sync(0xffffffffu, sA, 1);
        sA += __shfl_xor_sync(0xffffffffu, sA, 2);
        sB += __shfl_xor_sync(0xffffffffu, sB, 1);
        sB += __shfl_xor_sync(0xffffffffu, sB, 2);
        lA = lA * cA + sA;
        lB = lB * cB + sB;
#pragma unroll
        for (int nt = 0; nt < 8; nt++) {
            O[nt][0] *= cA; O[nt][1] *= cA;
            O[nt][2] *= cB; O[nt][3] *= cB;
        }

        // PV
#pragma unroll
        for (int sg = 0; sg < 4; sg++) {
            uint32_t ph[4], pl[4];
            {
                float f00 = sc[2 * sg][0], f01 = sc[2 * sg][1];
                float f02 = sc[2 * sg][2], f03 = sc[2 * sg][3];
                float f10 = sc[2 * sg + 1][0], f11 = sc[2 * sg + 1][1];
                float f12 = sc[2 * sg + 1][2], f13 = sc[2 * sg + 1][3];
                __half h00 = __float2half_rn(f00), h01 = __float2half_rn(f01);
                __half h02 = __float2half_rn(f02), h03 = __float2half_rn(f03);
                __half h10 = __float2half_rn(f10), h11 = __float2half_rn(f11);
                __half h12 = __float2half_rn(f12), h13 = __float2half_rn(f13);
                __half2 t;
                t.x = h00; t.y = h01; ph[0] = *(uint32_t*)&t;
                t.x = h02; t.y = h03; ph[1] = *(uint32_t*)&t;
                t.x = h10; t.y = h11; ph[2] = *(uint32_t*)&t;
                t.x = h12; t.y = h13; ph[3] = *(uint32_t*)&t;
                pl[0] = pack_h2(f00 - __half2float(h00), f01 - __half2float(h01));
                pl[1] = pack_h2(f02 - __half2float(h02), f03 - __half2float(h03));
                pl[2] = pack_h2(f10 - __half2float(h10), f11 - __half2float(h11));
                pl[3] = pack_h2(f12 - __half2float(h12), f13 - __half2float(h13));
            }
#pragma unroll
            for (int dg = 0; dg < 4; dg++) {
                int b_r = dg * 16 + b_rbase;
                uint32_t off = (uint32_t)(b_r * 128) + (((uint32_t)(sg * 32) + bsel) ^ ((uint32_t)((b_r & 7) << 4)));
                uint32_t vh4[4], vl4[4];
                ldsm4(vh4, vb + off);
                ldsm4(vl4, vlb + off);
#pragma unroll
                for (int n2 = 0; n2 < 2; n2++) {
                    float* o = O[2 * dg + n2];
                    mma_f16(o, ph, &vh4[n2 * 2]);
                    mma_f16(o, pl, &vh4[n2 * 2]);
                    mma_f16(o, ph, &vl4[n2 * 2]);
                }
            }
        }
        __syncthreads();
    }

    // epilogue: o hi/lo fp16
    float iA = 1.f / lA, iB = 1.f / lB;
    size_t r0o = (size_t)q0 * QDIM + h * 64;
    size_t r1o = r0o + (size_t)8 * QDIM;
#pragma unroll
    for (int nt = 0; nt < 8; nt++) {
        int c = nt * 8 + 2 * (lane & 3);
        float f0 = O[nt][0] * iA, f1 = O[nt][1] * iA;
        float f2 = O[nt][2] * iB, f3 = O[nt][3] * iB;
        __half h0 = __float2half_rn(f0), h1 = __float2half_rn(f1);
        __half h2 = __float2half_rn(f2), h3 = __float2half_rn(f3);
        __half2 t;
        t.x = h0; t.y = h1; *(__half2*)(g_o_h + r0o + c) = t;
        t.x = h2; t.y = h3; *(__half2*)(g_o_h + r1o + c) = t;
        uint32_t u;
        u = pack_h2(f0 - __half2float(h0), f1 - __half2float(h1));
        *(uint32_t*)(g_o_l + r0o + c) = u;
        u = pack_h2(f2 - __half2float(h2), f3 - __half2float(h3));
        *(uint32_t*)(g_o_l + r1o + c) = u;
    }
}

// ============================================================
// launch
// ============================================================
extern "C" void kernel_launch(void* const* d_in, const int* in_sizes, int n_in,
                              void* d_out, int out_size) {
    const float* x          = (const float*)d_in[0];
    const float* sinks      = (const float*)d_in[1];
    const float* norm_scale = (const float*)d_in[2];
    const float* qkv_w      = (const float*)d_in[3];
    const float* qkv_b      = (const float*)d_in[4];
    const float* out_w      = (const float*)d_in[5];
    const float* out_b      = (const float*)d_in[6];
    float* out = (float*)d_out;

    float* g_qkv_p; cudaGetSymbolAddress((void**)&g_qkv_p, g_qkv);
    __half *th, *tl, *w1, *w2, *oh, *ol;
    cudaGetSymbolAddress((void**)&th, g_t_h);
    cudaGetSymbolAddress((void**)&tl, g_t_l);
    cudaGetSymbolAddress((void**)&w1, g_w1);
    cudaGetSymbolAddress((void**)&w2, g_w2);
    cudaGetSymbolAddress((void**)&oh, g_o_h);
    cudaGetSymbolAddress((void**)&ol, g_o_l);

    cudaFuncSetAttribute(gemm_mma<false>, cudaFuncAttributeMaxDynamicSharedMemorySize, SMEM_TOTAL_GEMM);
    cudaFuncSetAttribute(gemm_mma<true>,  cudaFuncAttributeMaxDynamicSharedMemorySize, SMEM_TOTAL_GEMM);
    cudaFuncSetAttribute(attn_mma_kernel, cudaFuncAttributeMaxDynamicSharedMemorySize, ATT_SMEM_TOTAL);

    rope_tables_kernel<<<(S_TOK * 32 + 255) / 256, 256>>>();
    {
        int n4 = QKV_DIM * HID / 4;
        convert_h_kernel<<<(n4 + 255) / 256, 256>>>((const float4*)qkv_w, (uint2*)w1, n4);
    }
    {
        int n4 = HID * QDIM / 4;
        convert_h_kernel<<<(n4 + 255) / 256, 256>>>((const float4*)out_w, (uint2*)w2, n4);
    }

    rmsnorm_kernel<<<S_TOK, 256>>>(x, norm_scale);

    // qkv = t @ qkv_w^T + qkv_b   (M=1536, N=5120, K=2880)
    gemm_mma<false><<<dim3(QKV_DIM / BN, S_TOK / BM), 256, SMEM_TOTAL_GEMM>>>(
        th, tl, w1, qkv_b, nullptr, g_qkv_p, S_TOK, QKV_DIM, HID);

    // rope + split + v transpose
    prep_attn_kernel<<<S_TOK, 128>>>();

    // tensorized attention
    attn_mma_kernel<<<dim3(S_TOK / 64, NH), 128, ATT_SMEM_TOTAL>>>(sinks);

    // y = o @ out_w^T + out_b + x   (M=1536, N=2880, K=4096)
    gemm_mma<true><<<dim3((HID + BN - 1) / BN, S_TOK / BM), 256, SMEM_TOTAL_GEMM>>>(
        oh, ol, w2, out_b, x, out, S_TOK, HID, QDIM);
}

// round 5
// speedup vs baseline: 6.4925x; 1.6129x over previous
#include <cuda_runtime.h>
#include <cuda_fp16.h>
#include <cstdint>
#include <math.h>

// ---------------- problem constants ----------------
#define S_TOK   1536
#define HID     2880
#define NH      64
#define NKV     8
#define DH      64
#define QKV_DIM 5120
#define QDIM    4096
#define KOFF    4096
#define VOFF    4608
#define SM_SCALE 0.125f

// ---------------- scratch ----------------
__device__ float g_qkv[S_TOK * QKV_DIM];
__device__ __half g_t_h[S_TOK * HID];
__device__ __half g_w1[QKV_DIM * HID];
__device__ __half g_w2[HID * QDIM];
__device__ __half g_q_h[S_TOK * QDIM];
__device__ __half g_q_l[S_TOK * QDIM];
__device__ __half g_k_h[NKV * S_TOK * DH];
__device__ __half g_vt_h[NKV * DH * S_TOK];
__device__ __half g_o_h[S_TOK * QDIM];
__device__ float g_cos[S_TOK * 32];
__device__ float g_sin[S_TOK * 32];

// ---------------- helpers ----------------
__device__ __forceinline__ uint32_t smem_u32(const void* p) {
    uint32_t a;
    asm("{ .reg .u64 t; cvta.to.shared.u64 t, %1; cvt.u32.u64 %0, t; }" : "=r"(a) : "l"(p));
    return a;
}

__device__ __forceinline__ void ldsm4(uint32_t* r, uint32_t addr) {
    asm volatile("ldmatrix.sync.aligned.m8n8.x4.shared.b16 {%0,%1,%2,%3}, [%4];"
                 : "=r"(r[0]), "=r"(r[1]), "=r"(r[2]), "=r"(r[3]) : "r"(addr));
}

__device__ __forceinline__ void mma_f16(float* c, const uint32_t* a, const uint32_t* b) {
    asm volatile("mma.sync.aligned.m16n8k16.row.col.f32.f16.f16.f32 "
                 "{%0,%1,%2,%3}, {%4,%5,%6,%7}, {%8,%9}, {%0,%1,%2,%3};"
                 : "+f"(c[0]), "+f"(c[1]), "+f"(c[2]), "+f"(c[3])
                 : "r"(a[0]), "r"(a[1]), "r"(a[2]), "r"(a[3]), "r"(b[0]), "r"(b[1]));
}

__device__ __forceinline__ uint32_t pack_h2(float a, float b) {
    __half2 h = __floats2half2_rn(a, b);
    return *(uint32_t*)&h;
}

// ============================================================
// 1) RMSNorm -> fp16 (hi only)
// ============================================================
__global__ void rmsnorm_kernel(const float* __restrict__ x,
                               const float* __restrict__ scale) {
    int s = blockIdx.x;
    const float4* xr = (const float4*)(x + (size_t)s * HID);
    const float4* sc = (const float4*)scale;

    float ss = 0.f;
    for (int i = threadIdx.x; i < HID / 4; i += blockDim.x) {
        float4 v = xr[i];
        ss += v.x * v.x + v.y * v.y + v.z * v.z + v.w * v.w;
    }
    for (int o = 16; o > 0; o >>= 1) ss += __shfl_xor_sync(0xffffffff, ss, o);
    __shared__ float red[8];
    int wid = threadIdx.x >> 5, lid = threadIdx.x & 31;
    if (lid == 0) red[wid] = ss;
    __syncthreads();
    if (wid == 0) {
        float v = (lid < (blockDim.x >> 5)) ? red[lid] : 0.f;
        for (int o = 4; o > 0; o >>= 1) v += __shfl_xor_sync(0xffffffff, v, o);
        if (lid == 0) red[0] = v;
    }
    __syncthreads();
    float r = rsqrtf(red[0] / (float)HID + 1e-5f);

    uint2* th = (uint2*)(g_t_h + (size_t)s * HID);
    for (int i = threadIdx.x; i < HID / 4; i += blockDim.x) {
        float4 v = xr[i];
        float4 g = sc[i];
        uint2 hh;
        hh.x = pack_h2(v.x * r * g.x, v.y * r * g.y);
        hh.y = pack_h2(v.z * r * g.z, v.w * r * g.w);
        th[i] = hh;
    }
}

// ============================================================
// 2) fp32 -> fp16 convert (weights)
// ============================================================
__global__ void convert_h_kernel(const float4* __restrict__ src,
                                 uint2* __restrict__ dst, int n4) {
    int i = blockIdx.x * blockDim.x + threadIdx.x;
    if (i >= n4) return;
    float4 v = src[i];
    uint2 o;
    o.x = pack_h2(v.x, v.y);
    o.y = pack_h2(v.z, v.w);
    dst[i] = o;
}

// ============================================================
// 3) mma.sync fp16 GEMM: C = A B^T + bias (+resid)
//    CTA 128x128x64, 256 threads, warp tile 64x32
// ============================================================
#define BM 128
#define BN 128
#define BK 64
#define TILE_B 16384            // 128 rows x 128 bytes
#define STAGE_B (2 * TILE_B)    // A, B
#define GEMM_STAGES 3
#define SMEM_TOTAL_GEMM (GEMM_STAGES * STAGE_B + 1024)

__device__ __forceinline__ void load_tile_256(uint32_t sbase, const __half* __restrict__ g,
                                              int row0, int nrows, int ldk, int k0, int tid) {
#pragma unroll
    for (int u = 0; u < 4; u++) {
        int unit = u * 256 + tid;
        int r = unit >> 3;
        int c16 = unit & 7;
        uint32_t off = (uint32_t)(r * 128 + ((c16 * 16) ^ ((r & 7) << 4)));
        int gr = row0 + r;
        int ok = (gr < nrows) ? 16 : 0;
        const __half* src = g + (size_t)((gr < nrows) ? gr : 0) * ldk + k0 + c16 * 8;
        asm volatile("cp.async.cg.shared.global [%0], [%1], 16, %2;"
                     :: "r"(sbase + off), "l"(src), "r"(ok) : "memory");
    }
}

__device__ __forceinline__ void load_stage(uint32_t st,
                                           const __half* A, const __half* B,
                                           int bm, int bn, int M, int N, int K, int k0, int tid) {
    load_tile_256(st,          A, bm, M, K, k0, tid);
    load_tile_256(st + TILE_B, B, bn, N, K, k0, tid);
}

template <bool RESID>
__global__ void __launch_bounds__(256, 2)
gemm_mma(const __half* __restrict__ A, const __half* __restrict__ B,
         const float* __restrict__ bias, const float* __restrict__ resid,
         float* __restrict__ C, int M, int N, int K) {
    extern __shared__ char smem_raw[];
    uint32_t sb = (smem_u32(smem_raw) + 1023u) & ~1023u;

    const int tid = threadIdx.x;
    const int wid = tid >> 5;
    const int lane = tid & 31;
    const int wm = wid & 1;
    const int wn = wid >> 1;
    const int bm = blockIdx.y * BM;
    const int bn = blockIdx.x * BN;

    float acc[4][4][4];
#pragma unroll
    for (int i = 0; i < 4; i++)
#pragma unroll
        for (int j = 0; j < 4; j++)
#pragma unroll
            for (int k = 0; k < 4; k++) acc[i][j][k] = 0.f;

    const int a_r = wm * 64 + (lane & 15);
    const uint32_t a_cx = (uint32_t)((a_r & 7) << 4);
    const int b_r = wn * 32 + ((lane >> 4) << 3) + (lane & 7);
    const uint32_t b_cx = (uint32_t)((b_r & 7) << 4);

    const int NC = K / BK;

#pragma unroll
    for (int c = 0; c < 2; c++) {
        load_stage(sb + c * STAGE_B, A, B, bm, bn, M, N, K, c * BK, tid);
        asm volatile("cp.async.commit_group;" ::: "memory");
    }

    for (int c = 0; c < NC; c++) {
        int pf = c + 2;
        if (pf < NC) {
            load_stage(sb + (pf % GEMM_STAGES) * STAGE_B, A, B, bm, bn, M, N, K, pf * BK, tid);
        }
        asm volatile("cp.async.commit_group;" ::: "memory");
        asm volatile("cp.async.wait_group 2;" ::: "memory");
        __syncthreads();

        const uint32_t st = sb + (c % GEMM_STAGES) * STAGE_B;
#pragma unroll
        for (int ks = 0; ks < 4; ks++) {
            uint32_t ah[4][4], bh[2][4];
            const uint32_t acb = (uint32_t)(ks * 32 + ((lane >> 4) << 4));
#pragma unroll
            for (int mt = 0; mt < 4; mt++) {
                uint32_t off = (uint32_t)((a_r + mt * 16) * 128) + (acb ^ a_cx);
                ldsm4(ah[mt], st + off);
            }
            const uint32_t bcb = (uint32_t)(ks * 32 + ((lane >> 3) & 1) * 16);
#pragma unroll
            for (int p = 0; p < 2; p++) {
                uint32_t off = (uint32_t)((b_r + p * 16) * 128) + (bcb ^ b_cx);
                ldsm4(bh[p], st + TILE_B + off);
            }
#pragma unroll
            for (int mt = 0; mt < 4; mt++) {
#pragma unroll
                for (int nt = 0; nt < 4; nt++) {
                    mma_f16(acc[mt][nt], ah[mt], &bh[nt >> 1][(nt & 1) * 2]);
                }
            }
        }
        __syncthreads();
    }

    const int row0 = bm + wm * 64;
    const int col0 = bn + wn * 32;
#pragma unroll
    for (int mt = 0; mt < 4; mt++) {
#pragma unroll
        for (int nt = 0; nt < 4; nt++) {
            int r = row0 + mt * 16 + (lane >> 2);
            int c0 = col0 + nt * 8 + (lane & 3) * 2;
            if (c0 < N) {
                float bx = bias[c0], by = bias[c0 + 1];
                float2 v0, v1;
                v0.x = acc[mt][nt][0] + bx; v0.y = acc[mt][nt][1] + by;
                v1.x = acc[mt][nt][2] + bx; v1.y = acc[mt][nt][3] + by;
                if (RESID) {
                    const float2 x0 = *(const float2*)(resid + (size_t)r * N + c0);
                    const float2 x1 = *(const float2*)(resid + (size_t)(r + 8) * N + c0);
                    v0.x += x0.x; v0.y += x0.y;
                    v1.x += x1.x; v1.y += x1.y;
                }
                *(float2*)(C + (size_t)r * N + c0) = v0;
                *(float2*)(C + (size_t)(r + 8) * N + c0) = v1;
            }
        }
    }
}

// ============================================================
// 4) YaRN RoPE tables (fp64, matches reference)
// ============================================================
__global__ void rope_tables_kernel() {
    int gid = blockIdx.x * blockDim.x + threadIdx.x;
    if (gid >= S_TOK * 32) return;
    int s = gid >> 5;
    int i = gid & 31;
    const double TWO_PI = 6.283185307179586;
    double freq = pow(150000.0, (double)(2 * i) / 64.0);
    double conc = 0.1 * log(32.0) + 1.0;
    double lo = 32.0 * log(4096.0 / (32.0 * TWO_PI)) / log(150000.0);
    double hi = 32.0 * log(4096.0 / (1.0 * TWO_PI)) / log(150000.0);
    double interp = 1.0 / (32.0 * freq);
    double extrap = 1.0 / freq;
    double ramp = ((double)i - lo) / (hi - lo);
    double mask = 1.0 - fmin(fmax(ramp, 0.0), 1.0);
    double invf = interp * (1.0 - mask) + extrap * mask;
    double f = (double)s * invf;
    g_cos[gid] = (float)(cos(f) * conc);
    g_sin[gid] = (float)(sin(f) * conc);
}

// ============================================================
// 5) prep: rope + scale; q hi/lo, k hi, v hi transposed
// ============================================================
__global__ void __launch_bounds__(128)
prep_attn_kernel() {
    int s = blockIdx.x;
    int tid = threadIdx.x;
    __shared__ float cs[32], sn[32];
    if (tid < 32) { cs[tid] = g_cos[s * 32 + tid]; sn[tid] = g_sin[s * 32 + tid]; }
    __syncthreads();
    const float* row = g_qkv + (size_t)s * QKV_DIM;

    // q: 64 heads x 32 rotation pairs, scaled, hi/lo
    for (int i = tid; i < 2048; i += 128) {
        int hh = i >> 5, d = i & 31;
        float x1 = row[hh * 64 + d], x2 = row[hh * 64 + 32 + d];
        float c = cs[d], ss = sn[d];
        float r1 = (x1 * c - x2 * ss) * SM_SCALE;
        float r2 = (x2 * c + x1 * ss) * SM_SCALE;
        size_t o = (size_t)s * QDIM + hh * 64 + d;
        __half h1 = __float2half_rn(r1), h2 = __float2half_rn(r2);
        g_q_h[o] = h1; g_q_h[o + 32] = h2;
        g_q_l[o] = __float2half_rn(r1 - __half2float(h1));
        g_q_l[o + 32] = __float2half_rn(r2 - __half2float(h2));
    }
    // k: 8 kv heads x 32 pairs, layout [kv][s][64], hi only
    for (int i = tid; i < 256; i += 128) {
        int kvh = i >> 5, d = i & 31;
        float x1 = row[KOFF + kvh * 64 + d], x2 = row[KOFF + kvh * 64 + 32 + d];
        float c = cs[d], ss = sn[d];
        size_t o = (size_t)kvh * S_TOK * DH + (size_t)s * DH + d;
        g_k_h[o]      = __float2half_rn(x1 * c - x2 * ss);
        g_k_h[o + 32] = __float2half_rn(x2 * c + x1 * ss);
    }
    // v: transpose -> [kv][d][s], hi only
    for (int i = tid; i < 512; i += 128) {
        int kvh = i >> 6, d = i & 63;
        float v = row[VOFF + kvh * 64 + d];
        g_vt_h[(size_t)kvh * DH * S_TOK + (size_t)d * S_TOK + s] = __float2half_rn(v);
    }
}

// ============================================================
// 6) tensorized flash attention with sinks
//    block: 64 q rows x 1 head, 4 warps (16 rows each)
// ============================================================
#define ATT_STAGE 16384         // kh 8KB + vh 8KB
#define ATT_SMEM_TOTAL (1024 + 16384 + 2 * ATT_STAGE)

__device__ __forceinline__ void stage64(uint32_t sbase, const __half* __restrict__ g,
                                        int row_stride, int tid) {
#pragma unroll
    for (int u = 0; u < 4; u++) {
        int unit = u * 128 + tid;
        int r = unit >> 3, c16 = unit & 7;
        uint32_t off = (uint32_t)(r * 128 + ((c16 * 16) ^ ((r & 7) << 4)));
        const __half* src = g + (size_t)r * row_stride + c16 * 8;
        asm volatile("cp.async.cg.shared.global [%0], [%1], 16;"
                     :: "r"(sbase + off), "l"(src) : "memory");
    }
}

__device__ __forceinline__ void stage_kv(uint32_t base, int kt, int kv, int tid) {
    const __half* kh = g_k_h + (size_t)kv * S_TOK * DH + (size_t)kt * 64 * DH;
    const __half* vh = g_vt_h + (size_t)kv * DH * S_TOK + kt * 64;
    stage64(base,        kh, DH, tid);
    stage64(base + 8192, vh, S_TOK, tid);
}

__global__ void __launch_bounds__(128)
attn_mma_kernel(const float* __restrict__ sinks) {
    extern __shared__ char sraw[];
    uint32_t sb = (smem_u32(sraw) + 1023u) & ~1023u;
    const uint32_t QHB = sb, QLB = sb + 8192, KVB = sb + 16384;

    const int qt = blockIdx.x, h = blockIdx.y, kv = h & 7;
    const int tid = threadIdx.x, w = tid >> 5, lane = tid & 31;

    stage64(QHB, g_q_h + (size_t)(qt * 64) * QDIM + h * 64, QDIM, tid);
    stage64(QLB, g_q_l + (size_t)(qt * 64) * QDIM + h * 64, QDIM, tid);
    stage_kv(KVB, 0, kv, tid);
    asm volatile("cp.async.commit_group;" ::: "memory");
    asm volatile("cp.async.wait_group 0;" ::: "memory");
    __syncthreads();

    uint32_t qh[4][4], ql[4][4];
    {
        int a_r = w * 16 + (lane & 15);
        uint32_t ax = (uint32_t)((a_r & 7) << 4);
#pragma unroll
        for (int kt4 = 0; kt4 < 4; kt4++) {
            uint32_t cb = (uint32_t)(kt4 * 32 + ((lane >> 4) << 4));
            uint32_t off = (uint32_t)(a_r * 128) + (cb ^ ax);
            ldsm4(qh[kt4], QHB + off);
            ldsm4(ql[kt4], QLB + off);
        }
    }

    float O[8][4];
#pragma unroll
    for (int nt = 0; nt < 8; nt++)
#pragma unroll
        for (int j = 0; j < 4; j++) O[nt][j] = 0.f;

    float mA = sinks[h], mB = mA, lA = 1.f, lB = 1.f;
    const int q0 = qt * 64 + w * 16 + (lane >> 2);
    const int b_rbase = ((lane >> 4) << 3) + (lane & 7);
    const uint32_t bsel = (uint32_t)(((lane >> 3) & 1) * 16);

    for (int kt = 0; kt <= qt; kt++) {
        if (kt + 1 <= qt)
            stage_kv(KVB + ((kt + 1) & 1) * ATT_STAGE, kt + 1, kv, tid);
        asm volatile("cp.async.commit_group;" ::: "memory");
        asm volatile("cp.async.wait_group 1;" ::: "memory");
        __syncthreads();

        const uint32_t kb = KVB + (kt & 1) * ATT_STAGE;
        const uint32_t vb = kb + 8192;

        float sc[8][4];
#pragma unroll
        for (int nt = 0; nt < 8; nt++)
#pragma unroll
            for (int j = 0; j < 4; j++) sc[nt][j] = 0.f;

#pragma unroll
        for (int kt4 = 0; kt4 < 4; kt4++) {
#pragma unroll
            for (int kg = 0; kg < 4; kg++) {
                int b_r = kg * 16 + b_rbase;
                uint32_t off = (uint32_t)(b_r * 128) + (((uint32_t)(kt4 * 32) + bsel) ^ ((uint32_t)((b_r & 7) << 4)));
                uint32_t bh4[4];
                ldsm4(bh4, kb + off);
#pragma unroll
                for (int n2 = 0; n2 < 2; n2++) {
                    float* s = sc[2 * kg + n2];
                    mma_f16(s, qh[kt4], &bh4[n2 * 2]);
                    mma_f16(s, ql[kt4], &bh4[n2 * 2]);
                }
            }
        }

        if (kt == qt) {
#pragma unroll
            for (int nt = 0; nt < 8; nt++) {
                int key = kt * 64 + nt * 8 + 2 * (lane & 3);
                if (key > q0)         sc[nt][0] = -1e30f;
                if (key + 1 > q0)     sc[nt][1] = -1e30f;
                if (key > q0 + 8)     sc[nt][2] = -1e30f;
                if (key + 1 > q0 + 8) sc[nt][3] = -1e30f;
            }
        }

        float r0 = -1e30f, r1 = -1e30f;
#pragma unroll
        for (int nt = 0; nt < 8; nt++) {
            r0 = fmaxf(r0, fmaxf(sc[nt][0], sc[nt][1]));
            r1 = fmaxf(r1, fmaxf(sc[nt][2], sc[nt][3]));
        }
        r0 = fmaxf(r0, __shfl_xor_sync(0xffffffffu, r0, 1));
        r0 = fmaxf(r0, __shfl_xor_sync(0xffffffffu, r0, 2));
        r1 = fmaxf(r1, __shfl_xor_sync(0xffffffffu, r1, 1));
        r1 = fmaxf(r1, __shfl_xor_sync(0xffffffffu, r1, 2));
        float mA2 = fmaxf(mA, r0), mB2 = fmaxf(mB, r1);
        float cA = __expf(mA - mA2), cB = __expf(mB - mB2);
        mA = mA2; mB = mB2;

        float sA = 0.f, sB = 0.f;
#pragma unroll
        for (int nt = 0; nt < 8; nt++) {
            sc[nt][0] = __expf(sc[nt][0] - mA);
            sc[nt][1] = __expf(sc[nt][1] - mA);
            sc[nt][2] = __expf(sc[nt][2] - mB);
            sc[nt][3] = __expf(sc[nt][3] - mB);
            sA += sc[nt][0] + sc[nt][1];
            sB += sc[nt][2] + sc[nt][3];
        }
        sA += __shfl_xor_sync(0xffffffffu, sA, 1);
        sA += __shfl_xor_sync(0xffffffffu, sA, 2);
        sB += __shfl_xor_sync(0xffffffffu, sB, 1);
        sB += __shfl_xor_sync(0xffffffffu, sB, 2);
        lA = lA * cA + sA;
        lB = lB * cB + sB;
#pragma unroll
        for (int nt = 0; nt < 8; nt++) {
            O[nt][0] *= cA; O[nt][1] *= cA;
            O[nt][2] *= cB; O[nt][3] *= cB;
        }

        // PV: p split hi/lo, v hi only
#pragma unroll
        for (int sg = 0; sg < 4; sg++) {
            uint32_t ph[4], pl[4];
            {
                float f00 = sc[2 * sg][0], f01 = sc[2 * sg][1];
                float f02 = sc[2 * sg][2], f03 = sc[2 * sg][3];
                float f10 = sc[2 * sg + 1][0], f11 = sc[2 * sg + 1][1];
                float f12 = sc[2 * sg + 1][2], f13 = sc[2 * sg + 1][3];
                __half h00 = __float2half_rn(f00), h01 = __float2half_rn(f01);
                __half h02 = __float2half_rn(f02), h03 = __float2half_rn(f03);
                __half h10 = __float2half_rn(f10), h11 = __float2half_rn(f11);
                __half h12 = __float2half_rn(f12), h13 = __float2half_rn(f13);
                __half2 t;
                t.x = h00; t.y = h01; ph[0] = *(uint32_t*)&t;
                t.x = h02; t.y = h03; ph[1] = *(uint32_t*)&t;
                t.x = h10; t.y = h11; ph[2] = *(uint32_t*)&t;
                t.x = h12; t.y = h13; ph[3] = *(uint32_t*)&t;
                pl[0] = pack_h2(f00 - __half2float(h00), f01 - __half2float(h01));
                pl[1] = pack_h2(f02 - __half2float(h02), f03 - __half2float(h03));
                pl[2] = pack_h2(f10 - __half2float(h10), f11 - __half2float(h11));
                pl[3] = pack_h2(f12 - __half2float(h12), f13 - __half2float(h13));
            }
#pragma unroll
            for (int dg = 0; dg < 4; dg++) {
                int b_r = dg * 16 + b_rbase;
                uint32_t off = (uint32_t)(b_r * 128) + (((uint32_t)(sg * 32) + bsel) ^ ((uint32_t)((b_r & 7) << 4)));
                uint32_t vh4[4];
                ldsm4(vh4, vb + off);
#pragma unroll
                for (int n2 = 0; n2 < 2; n2++) {
                    float* o = O[2 * dg + n2];
                    mma_f16(o, ph, &vh4[n2 * 2]);
                    mma_f16(o, pl, &vh4[n2 * 2]);
                }
            }
        }
        __syncthreads();
    }

    // epilogue: o hi fp16
    float iA = 1.f / lA, iB = 1.f / lB;
    size_t r0o = (size_t)q0 * QDIM + h * 64;
    size_t r1o = r0o + (size_t)8 * QDIM;
#pragma unroll
    for (int nt = 0; nt < 8; nt++) {
        int c = nt * 8 + 2 * (lane & 3);
        *(uint32_t*)(g_o_h + r0o + c) = pack_h2(O[nt][0] * iA, O[nt][1] * iA);
        *(uint32_t*)(g_o_h + r1o + c) = pack_h2(O[nt][2] * iB, O[nt][3] * iB);
    }
}

// ============================================================
// launch
// ============================================================
extern "C" void kernel_launch(void* const* d_in, const int* in_sizes, int n_in,
                              void* d_out, int out_size) {
    const float* x          = (const float*)d_in[0];
    const float* sinks      = (const float*)d_in[1];
    const float* norm_scale = (const float*)d_in[2];
    const float* qkv_w      = (const float*)d_in[3];
    const float* qkv_b      = (const float*)d_in[4];
    const float* out_w      = (const float*)d_in[5];
    const float* out_b      = (const float*)d_in[6];
    float* out = (float*)d_out;

    float* g_qkv_p; cudaGetSymbolAddress((void**)&g_qkv_p, g_qkv);
    __half *th, *w1, *w2, *oh;
    cudaGetSymbolAddress((void**)&th, g_t_h);
    cudaGetSymbolAddress((void**)&w1, g_w1);
    cudaGetSymbolAddress((void**)&w2, g_w2);
    cudaGetSymbolAddress((void**)&oh, g_o_h);

    cudaFuncSetAttribute(gemm_mma<false>, cudaFuncAttributeMaxDynamicSharedMemorySize, SMEM_TOTAL_GEMM);
    cudaFuncSetAttribute(gemm_mma<true>,  cudaFuncAttributeMaxDynamicSharedMemorySize, SMEM_TOTAL_GEMM);
    cudaFuncSetAttribute(attn_mma_kernel, cudaFuncAttributeMaxDynamicSharedMemorySize, ATT_SMEM_TOTAL);

    rope_tables_kernel<<<(S_TOK * 32 + 255) / 256, 256>>>();
    {
        int n4 = QKV_DIM * HID / 4;
        convert_h_kernel<<<(n4 + 255) / 256, 256>>>((const float4*)qkv_w, (uint2*)w1, n4);
    }
    {
        int n4 = HID * QDIM / 4;
        convert_h_kernel<<<(n4 + 255) / 256, 256>>>((const float4*)out_w, (uint2*)w2, n4);
    }

    rmsnorm_kernel<<<S_TOK, 256>>>(x, norm_scale);

    // qkv = t @ qkv_w^T + qkv_b   (M=1536, N=5120, K=2880)
    gemm_mma<false><<<dim3(QKV_DIM / BN, S_TOK / BM), 256, SMEM_TOTAL_GEMM>>>(
        th, w1, qkv_b, nullptr, g_qkv_p, S_TOK, QKV_DIM, HID);

    // rope + split + v transpose
    prep_attn_kernel<<<S_TOK, 128>>>();

    // tensorized attention
    attn_mma_kernel<<<dim3(S_TOK / 64, NH), 128, ATT_SMEM_TOTAL>>>(sinks);

    // y = o @ out_w^T + out_b + x   (M=1536, N=2880, K=4096)
    gemm_mma<true><<<dim3((HID + BN - 1) / BN, S_TOK / BM), 256, SMEM_TOTAL_GEMM>>>(
        oh, w2, out_b, x, out, S_TOK, HID, QDIM);
}